// round 16
// baseline (speedup 1.0000x reference)
#include <cuda_runtime.h>
#include <cuda_bf16.h>
#include <math.h>
#include <stdint.h>

#define N_NODES 100000
#define N_EDGES 1600000
#define VOCAB   2048
#define DIM     64
#define N_MASK  10000
#define M_PAD   10112   // 79 * 128 (GEMM2 row tiles)

// ---------------- scratch (device globals: allocation-free) ----------------
__device__ int   g_deg[N_NODES];        // zero at load; re-zeroed by scan_fused
__device__ int   g_rowptr[N_NODES + 1];
__device__ int   g_cursor[N_NODES];
__device__ int   g_tok[N_NODES];
__device__ int   g_colpk[N_EDGES];      // src | (tok[src] << 17)
__device__ int   g_agg[100];
__device__ unsigned g_pub;              // scan publish counter (self-resetting)
__device__ unsigned g_fin;              // scan finish counter (self-resetting)
__device__ float g_El[VOCAB * DIM];     // emb @ W_l1
__device__ float g_Er[VOCAB * DIM];     // emb @ W_r1
__device__ float g_h1[N_NODES * DIM];
__device__ __nv_bfloat16 g_x2h[M_PAD * 128];   // A tile bf16 hi (pad rows stay 0)
__device__ __nv_bfloat16 g_x2l[M_PAD * 128];   // A tile bf16 lo
__device__ __nv_bfloat16 g_w2h[VOCAB * 128];   // B[n][k] bf16 hi, n-major
__device__ __nv_bfloat16 g_w2l[VOCAB * 128];   // B[n][k] bf16 lo
__device__ float g_logits[N_MASK * 2048];

__device__ __forceinline__ int ld_idx(const void* p, long i, int is64) {
    return is64 ? (int)((const long long*)p)[i] : ((const int*)p)[i];
}

// per-block dtype detect: int64 little-endian => odd 32-bit words all zero
__device__ __forceinline__ int detect_is64(const void* edge, int* sh) {
    if (threadIdx.x < 32) {
        int v = ((const int*)edge)[2 * threadIdx.x + 1];
        unsigned nz = __ballot_sync(0xffffffffu, v != 0);
        if (threadIdx.x == 0) *sh = (nz == 0u) ? 1 : 0;
    }
    __syncthreads();
    return *sh;
}

// load 4 consecutive indices starting at i (i multiple of 4)
__device__ __forceinline__ void ld_idx4(const void* p, long i, int is64, int* o) {
    if (is64) {
        longlong2 a = *(const longlong2*)((const long long*)p + i);
        longlong2 b = *(const longlong2*)((const long long*)p + i + 2);
        o[0] = (int)a.x; o[1] = (int)a.y; o[2] = (int)b.x; o[3] = (int)b.y;
    } else {
        int4 a = *(const int4*)((const int*)p + i);
        o[0] = a.x; o[1] = a.y; o[2] = a.z; o[3] = a.w;
    }
}

// ---------------- single-pass scan (100 resident blocks, spin barrier) ------
__global__ void scan_fused() {
    __shared__ int s[256];
    __shared__ int aggs[100];
    int b = blockIdx.x, t = threadIdx.x;
    int o = b * 1000 + t * 4;
    int d0 = 0, d1 = 0, d2 = 0, d3 = 0, sum = 0;
    if (t < 250) {
        d0 = g_deg[o]; d1 = g_deg[o + 1]; d2 = g_deg[o + 2]; d3 = g_deg[o + 3];
        sum = d0 + d1 + d2 + d3;
    }
    s[t] = sum; __syncthreads();
    for (int off = 1; off < 256; off <<= 1) {          // inclusive scan
        int x = (t >= off) ? s[t - off] : 0;
        __syncthreads();
        s[t] += x;
        __syncthreads();
    }
    int total = s[255];

    if (t == 0) {
        g_agg[b] = total;
        __threadfence();
        atomicAdd(&g_pub, 1u);
        while (atomicAdd(&g_pub, 0u) < 100u) {}
        __threadfence();
    }
    __syncthreads();
    if (t < 100) aggs[t] = g_agg[t];
    __syncthreads();

    int boff = 0;
    for (int i = 0; i < b; i++) boff += aggs[i];

    if (t < 250) {
        int run = boff + s[t] - sum;                   // exclusive prefix
        g_rowptr[o] = run;     g_cursor[o] = run;     run += d0;
        g_rowptr[o + 1] = run; g_cursor[o + 1] = run; run += d1;
        g_rowptr[o + 2] = run; g_cursor[o + 2] = run; run += d2;
        g_rowptr[o + 3] = run; g_cursor[o + 3] = run;
        g_deg[o] = 0; g_deg[o + 1] = 0; g_deg[o + 2] = 0; g_deg[o + 3] = 0;
    }
    if (b == 99 && t == 255) g_rowptr[N_NODES] = boff + total;

    __threadfence();
    if (t == 0) {
        unsigned f = atomicAdd(&g_fin, 1u);
        if (f == 99u) { g_pub = 0u; g_fin = 0u; }
    }
}

// =============== bf16 split helpers ========================================
static __device__ __forceinline__ uint32_t pack_bf2(float a, float b) {
    __nv_bfloat162 t = __floats2bfloat162_rn(a, b);
    return reinterpret_cast<uint32_t&>(t);
}
static __device__ __forceinline__ void split8(const float* v, uint4& hi, uint4& lo) {
    float r[8];
#pragma unroll
    for (int i = 0; i < 8; i++)
        r[i] = v[i] - __bfloat162float(__float2bfloat16(v[i]));
    hi = make_uint4(pack_bf2(v[0], v[1]), pack_bf2(v[2], v[3]),
                    pack_bf2(v[4], v[5]), pack_bf2(v[6], v[7]));
    lo = make_uint4(pack_bf2(r[0], r[1]), pack_bf2(r[2], r[3]),
                    pack_bf2(r[4], r[5]), pack_bf2(r[6], r[7]));
}
static __device__ __forceinline__ void split2(float2 v, uint32_t& hi, uint32_t& lo) {
    float rx = v.x - __bfloat162float(__float2bfloat16(v.x));
    float ry = v.y - __bfloat162float(__float2bfloat16(v.y));
    hi = pack_bf2(v.x, v.y);
    lo = pack_bf2(rx, ry);
}

#define MMA16816(d, a, b) \
    asm volatile( \
        "mma.sync.aligned.m16n8k16.row.col.f32.bf16.bf16.f32 " \
        "{%0,%1,%2,%3}, {%4,%5,%6,%7}, {%8,%9}, {%0,%1,%2,%3};" \
        : "+f"((d)[0]), "+f"((d)[1]), "+f"((d)[2]), "+f"((d)[3]) \
        : "r"((a)[0]), "r"((a)[1]), "r"((a)[2]), "r"((a)[3]), \
          "r"((b)[0]), "r"((b)[1]))

#define GSTR 136                             // bf16 per smem row (conflict-free)
#define GT_SMEM ((128 + 64) * 2 * GSTR * 2)  // 104448 B

// ---------- prep (fused): hist, g_tok, W2 split, E_l/E_r GEMM ---------------
#define PREP_HIST_BLOCKS 1563   // ceil(1600000/4/256)
#define PREP_TOK_BLOCKS 391     // ceil(100000/256)
#define PREP_W2_BLOCKS  128     // 32768/256
#define PREP_E_BLOCKS   256     // 2048 rows / 8 warps
__global__ void prep_kernel(const void* x, const void* edge,
                            const float* __restrict__ emb,
                            const float* __restrict__ Wl1,
                            const float* __restrict__ Wr1,
                            const float* __restrict__ Wl2,
                            const float* __restrict__ Wr2) {
    __shared__ float2 sWl[64 * 32];
    __shared__ float2 sWr[64 * 32];
    int b = blockIdx.x, t = threadIdx.x;
    if (b < PREP_HIST_BLOCKS) {
        __shared__ int sh;
        int is64 = detect_is64(edge, &sh);
        long e = (b * 256L + t) * 4;
        if (e >= N_EDGES) return;
        int d[4];
        ld_idx4(edge, N_EDGES + e, is64, d);
        atomicAdd(&g_deg[d[0]], 1);
        atomicAdd(&g_deg[d[1]], 1);
        atomicAdd(&g_deg[d[2]], 1);
        atomicAdd(&g_deg[d[3]], 1);
    } else if (b < PREP_HIST_BLOCKS + PREP_TOK_BLOCKS) {
        __shared__ int sh;
        int is64 = detect_is64(edge, &sh);
        int n = (b - PREP_HIST_BLOCKS) * 256 + t;
        if (n < N_NODES) g_tok[n] = ld_idx(x, n, is64);
    } else if (b < PREP_HIST_BLOCKS + PREP_TOK_BLOCKS + PREP_W2_BLOCKS) {
        int p = (b - PREP_HIST_BLOCKS - PREP_TOK_BLOCKS) * 256 + t;   // 0..32767
        int n = p & 2047, koct = p >> 11;
        const float* W = (koct < 8) ? Wl2 : Wr2;
        int kr0 = (koct * 8) & 63;
        float v[8];
#pragma unroll
        for (int j = 0; j < 8; j++)
            v[j] = W[(long)(kr0 + j) * 2048 + n];
        uint4 hi, lo;
        split8(v, hi, lo);
        *(uint4*)&g_w2h[n * 128 + koct * 8] = hi;
        *(uint4*)&g_w2l[n * 128 + koct * 8] = lo;
    } else {
        // E GEMM: 8 warps/block, warp per emb row
        int lane = t & 31, wid = t >> 5;
        for (int idx = t; idx < 64 * 32; idx += 256) {
            int k = idx >> 5, c = idx & 31;
            sWl[idx] = make_float2(Wl1[k * 64 + c], Wl1[k * 64 + 32 + c]);
            sWr[idx] = make_float2(Wr1[k * 64 + c], Wr1[k * 64 + 32 + c]);
        }
        __syncthreads();
        int row = (b - PREP_HIST_BLOCKS - PREP_TOK_BLOCKS - PREP_W2_BLOCKS) * 8 + wid;
        float e0 = emb[row * 64 + lane];
        float e1 = emb[row * 64 + 32 + lane];
        float al0 = 0.f, al1 = 0.f, ar0 = 0.f, ar1 = 0.f;
#pragma unroll
        for (int k = 0; k < 32; k++) {
            float ek = __shfl_sync(0xffffffffu, e0, k);
            float2 wl = sWl[k * 32 + lane];
            float2 wr = sWr[k * 32 + lane];
            al0 += ek * wl.x; al1 += ek * wl.y;
            ar0 += ek * wr.x; ar1 += ek * wr.y;
        }
#pragma unroll
        for (int k = 0; k < 32; k++) {
            float ek = __shfl_sync(0xffffffffu, e1, k);
            float2 wl = sWl[(k + 32) * 32 + lane];
            float2 wr = sWr[(k + 32) * 32 + lane];
            al0 += ek * wl.x; al1 += ek * wl.y;
            ar0 += ek * wr.x; ar1 += ek * wr.y;
        }
        g_El[row * 64 + lane] = al0;  g_El[row * 64 + 32 + lane] = al1;
        g_Er[row * 64 + lane] = ar0;  g_Er[row * 64 + 32 + lane] = ar1;
    }
}

// ---------------- scatter: writes src | (tok[src] << 17), 4 edges/thread ----
__global__ void scatter_kernel(const void* edge) {
    __shared__ int sh;
    int is64 = detect_is64(edge, &sh);
    long t = blockIdx.x * (long)blockDim.x + threadIdx.x;
    long e = t * 4;
    if (e >= N_EDGES) return;
    int s[4], d[4];
    ld_idx4(edge, e, is64, s);
    ld_idx4(edge, N_EDGES + e, is64, d);
    int tk0 = g_tok[s[0]], tk1 = g_tok[s[1]], tk2 = g_tok[s[2]], tk3 = g_tok[s[3]];
    g_colpk[atomicAdd(&g_cursor[d[0]], 1)] = s[0] | (tk0 << 17);
    g_colpk[atomicAdd(&g_cursor[d[1]], 1)] = s[1] | (tk1 << 17);
    g_colpk[atomicAdd(&g_cursor[d[2]], 1)] = s[2] | (tk2 << 17);
    g_colpk[atomicAdd(&g_cursor[d[3]], 1)] = s[3] | (tk3 << 17);
}

// -------- fused SpMM mean + dense1: warp per node, float2 per lane ---------
// MLP=4; vectorized int4 colpk loads (aligned after peel); lane owns dims
// {2l, 2l+1}; no cross-lane reduction.
__global__ void spmm_h1_kernel(const float* __restrict__ bl1) {
    int nid = (blockIdx.x * blockDim.x + threadIdx.x) >> 5;
    int lane = threadIdx.x & 31;
    if (nid >= N_NODES) return;
    int start = g_rowptr[nid], end = g_rowptr[nid + 1];
    const float2* El2 = (const float2*)g_El;
    float2 a0 = make_float2(0.f, 0.f), a1 = a0, a2 = a0, a3 = a0;
    int p = start;
    int pre = (4 - (p & 3)) & 3;
    if (pre > end - p) pre = end - p;
    for (int i = 0; i < pre; i++, p++) {
        int t0 = ((unsigned)g_colpk[p]) >> 17;
        float2 v0 = El2[t0 * 32 + lane];
        a0.x += v0.x; a0.y += v0.y;
    }
    for (; p + 3 < end; p += 4) {
        int4 c = *(const int4*)&g_colpk[p];
        int t0 = ((unsigned)c.x) >> 17;
        int t1 = ((unsigned)c.y) >> 17;
        int t2 = ((unsigned)c.z) >> 17;
        int t3 = ((unsigned)c.w) >> 17;
        float2 v0 = El2[t0 * 32 + lane];
        float2 v1 = El2[t1 * 32 + lane];
        float2 v2 = El2[t2 * 32 + lane];
        float2 v3 = El2[t3 * 32 + lane];
        a0.x += v0.x; a0.y += v0.y;
        a1.x += v1.x; a1.y += v1.y;
        a2.x += v2.x; a2.y += v2.y;
        a3.x += v3.x; a3.y += v3.y;
    }
    for (; p < end; p++) {
        int t0 = ((unsigned)g_colpk[p]) >> 17;
        float2 v0 = El2[t0 * 32 + lane];
        a0.x += v0.x; a0.y += v0.y;
    }
    a0.x += a1.x + a2.x + a3.x;
    a0.y += a1.y + a2.y + a3.y;
    float inv = 1.0f / fmaxf((float)(end - start), 1.0f);
    int tokn = g_tok[nid];
    float2 er = ((const float2*)g_Er)[tokn * 32 + lane];
    float2 bb = ((const float2*)bl1)[lane];
    float2 o = make_float2(fmaxf(a0.x * inv + er.x + bb.x, 0.f),
                           fmaxf(a0.y * inv + er.y + bb.y, 0.f));
    ((float2*)g_h1)[(long)nid * 32 + lane] = o;
}

// ---------------- SpMM mean, layer 2: warp per node, int4 colpk loads -------
__global__ void spmm2_kernel(const void* mask, const void* edge) {
    __shared__ int sh;
    int is64 = detect_is64(edge, &sh);
    int wid = (blockIdx.x * blockDim.x + threadIdx.x) >> 5;
    int lane = threadIdx.x & 31;
    if (wid >= N_MASK) return;
    int n = ld_idx(mask, wid, is64);
    int start = g_rowptr[n], end = g_rowptr[n + 1];
    const float2* h = (const float2*)g_h1;
    float2 a0 = make_float2(0.f, 0.f), a1 = a0, a2 = a0, a3 = a0;
    int p = start;
    int pre = (4 - (p & 3)) & 3;
    if (pre > end - p) pre = end - p;
    for (int i = 0; i < pre; i++, p++) {
        int s0 = g_colpk[p] & 0x1FFFF;
        float2 v0 = h[(long)s0 * 32 + lane];
        a0.x += v0.x; a0.y += v0.y;
    }
    for (; p + 3 < end; p += 4) {
        int4 c = *(const int4*)&g_colpk[p];
        int s0 = c.x & 0x1FFFF, s1 = c.y & 0x1FFFF;
        int s2 = c.z & 0x1FFFF, s3 = c.w & 0x1FFFF;
        float2 v0 = h[(long)s0 * 32 + lane];
        float2 v1 = h[(long)s1 * 32 + lane];
        float2 v2 = h[(long)s2 * 32 + lane];
        float2 v3 = h[(long)s3 * 32 + lane];
        a0.x += v0.x; a0.y += v0.y;
        a1.x += v1.x; a1.y += v1.y;
        a2.x += v2.x; a2.y += v2.y;
        a3.x += v3.x; a3.y += v3.y;
    }
    for (; p < end; p++) {
        int s0 = g_colpk[p] & 0x1FFFF;
        float2 v0 = h[(long)s0 * 32 + lane];
        a0.x += v0.x; a0.y += v0.y;
    }
    a0.x += a1.x + a2.x + a3.x;
    a0.y += a1.y + a2.y + a3.y;
    float inv = 1.0f / fmaxf((float)(end - start), 1.0f);
    float2 vm = make_float2(a0.x * inv, a0.y * inv);
    float2 vs = h[(long)n * 32 + lane];
    uint32_t mh, ml, sh2, sl;
    split2(vm, mh, ml);
    split2(vs, sh2, sl);
    long bm = (long)wid * 128 + lane * 2;       // mean part (dims 0..63)
    long bs = bm + 64;                          // self part (dims 64..127)
    *(uint32_t*)&g_x2h[bm] = mh;  *(uint32_t*)&g_x2l[bm] = ml;
    *(uint32_t*)&g_x2h[bs] = sh2; *(uint32_t*)&g_x2l[bs] = sl;
}

// ====== GEMM2: 128-row blocks, 2 col-tiles per CTA (A reused), 2 CTA/SM =====
__global__ void __launch_bounds__(256, 2) gemm2_mma(const float* __restrict__ bl2) {
    extern __shared__ __nv_bfloat16 sm[];
    __nv_bfloat16* AH = sm;
    __nv_bfloat16* AL = sm + 128 * GSTR;
    __nv_bfloat16* BH = sm + 2 * 128 * GSTR;
    __nv_bfloat16* BL = sm + 2 * 128 * GSTR + 64 * GSTR;

    int tid = threadIdx.x;
    int lane = tid & 31, wid = tid >> 5;
    int rowBase = blockIdx.x * 128;

    // load A tile once; reused for 2 col tiles
#pragma unroll
    for (int it = 0; it < 8; it++) {
        int p = tid + it * 256;
        int m = p >> 4, koct = p & 15;
        long src = (long)(rowBase + m) * 128 + koct * 8;
        *(uint4*)&AH[m * GSTR + koct * 8] = *(const uint4*)&g_x2h[src];
        *(uint4*)&AL[m * GSTR + koct * 8] = *(const uint4*)&g_x2l[src];
    }

    int tig = lane & 3, grp = lane >> 2;
    int wm = (wid & 3) * 32;
    int wn = (wid >> 2) * 32;

#pragma unroll
    for (int ct = 0; ct < 2; ct++) {
        int colBase = (blockIdx.y * 2 + ct) * 64;
        __syncthreads();   // B consumers of prev iter done (covers A on ct=0)
#pragma unroll
        for (int it = 0; it < 4; it++) {
            int p = tid + it * 256;
            int n = p >> 4, koct = p & 15;
            long src = (long)(colBase + n) * 128 + koct * 8;
            *(uint4*)&BH[n * GSTR + koct * 8] = *(const uint4*)&g_w2h[src];
            *(uint4*)&BL[n * GSTR + koct * 8] = *(const uint4*)&g_w2l[src];
        }
        __syncthreads();

        float acc[2][4][4] = {};
#pragma unroll
        for (int ks = 0; ks < 8; ks++) {
            int kw = ks * 8 + tig;
            uint32_t aH[2][4], aL[2][4], bH[4][2], bL[4][2];
#pragma unroll
            for (int mt = 0; mt < 2; mt++) {
                const __nv_bfloat16* pH = &AH[(wm + mt * 16 + grp) * GSTR + kw * 2];
                const __nv_bfloat16* pL = &AL[(wm + mt * 16 + grp) * GSTR + kw * 2];
                aH[mt][0] = *(const uint32_t*)pH;
                aH[mt][1] = *(const uint32_t*)(pH + 8 * GSTR);
                aH[mt][2] = *(const uint32_t*)(pH + 8);
                aH[mt][3] = *(const uint32_t*)(pH + 8 * GSTR + 8);
                aL[mt][0] = *(const uint32_t*)pL;
                aL[mt][1] = *(const uint32_t*)(pL + 8 * GSTR);
                aL[mt][2] = *(const uint32_t*)(pL + 8);
                aL[mt][3] = *(const uint32_t*)(pL + 8 * GSTR + 8);
            }
#pragma unroll
            for (int nt = 0; nt < 4; nt++) {
                const __nv_bfloat16* pH = &BH[(wn + nt * 8 + grp) * GSTR + kw * 2];
                const __nv_bfloat16* pL = &BL[(wn + nt * 8 + grp) * GSTR + kw * 2];
                bH[nt][0] = *(const uint32_t*)pH;
                bH[nt][1] = *(const uint32_t*)(pH + 8);
                bL[nt][0] = *(const uint32_t*)pL;
                bL[nt][1] = *(const uint32_t*)(pL + 8);
            }
#pragma unroll
            for (int mt = 0; mt < 2; mt++)
#pragma unroll
                for (int nt = 0; nt < 4; nt++) {
                    MMA16816(acc[mt][nt], aH[mt], bH[nt]);
                    MMA16816(acc[mt][nt], aH[mt], bL[nt]);
                    MMA16816(acc[mt][nt], aL[mt], bH[nt]);
                }
        }

#pragma unroll
        for (int mt = 0; mt < 2; mt++) {
#pragma unroll
            for (int nt = 0; nt < 4; nt++) {
                int row = rowBase + wm + mt * 16 + grp;
                int col = colBase + wn + nt * 8 + tig * 2;
                float2 bv = *(const float2*)&bl2[col];
                if (row < N_MASK) {
                    float2 o = make_float2(acc[mt][nt][0] + bv.x, acc[mt][nt][1] + bv.y);
                    *(float2*)&g_logits[(long)row * 2048 + col] = o;
                }
                if (row + 8 < N_MASK) {
                    float2 o = make_float2(acc[mt][nt][2] + bv.x, acc[mt][nt][3] + bv.y);
                    *(float2*)&g_logits[(long)(row + 8) * 2048 + col] = o;
                }
            }
        }
    }
}

// ---------------- row-wise log_softmax --------------------------------------
__global__ void softmax_kernel(float* out) {
    __shared__ float sred[256];
    int r = blockIdx.x;
    int t = threadIdx.x;
    const float4* L = (const float4*)&g_logits[(long)r * 2048];
    float4 v0 = L[t], v1 = L[t + 256];

    float mx = fmaxf(fmaxf(fmaxf(v0.x, v0.y), fmaxf(v0.z, v0.w)),
                     fmaxf(fmaxf(v1.x, v1.y), fmaxf(v1.z, v1.w)));
    sred[t] = mx; __syncthreads();
    for (int s = 128; s > 0; s >>= 1) {
        if (t < s) sred[t] = fmaxf(sred[t], sred[t + s]);
        __syncthreads();
    }
    mx = sred[0];
    __syncthreads();

    float sum = __expf(v0.x - mx) + __expf(v0.y - mx) + __expf(v0.z - mx) + __expf(v0.w - mx)
              + __expf(v1.x - mx) + __expf(v1.y - mx) + __expf(v1.z - mx) + __expf(v1.w - mx);
    sred[t] = sum; __syncthreads();
    for (int s = 128; s > 0; s >>= 1) {
        if (t < s) sred[t] += sred[t + s];
        __syncthreads();
    }
    float shift = mx + logf(sred[0]);

    float4* O = (float4*)&out[(long)r * 2048];
    O[t]       = make_float4(v0.x - shift, v0.y - shift, v0.z - shift, v0.w - shift);
    O[t + 256] = make_float4(v1.x - shift, v1.y - shift, v1.z - shift, v1.w - shift);
}

// ---------------- launch ----------------------------------------------------
extern "C" void kernel_launch(void* const* d_in, const int* in_sizes, int n_in,
                              void* d_out, int out_size) {
    const void*  x    = d_in[0];
    const void*  edge = d_in[1];
    const void*  mask = d_in[2];
    const float* emb  = (const float*)d_in[3];
    const float* Wl1  = (const float*)d_in[4];
    const float* bl1  = (const float*)d_in[5];
    const float* Wr1  = (const float*)d_in[6];
    const float* Wl2  = (const float*)d_in[7];
    const float* bl2  = (const float*)d_in[8];
    const float* Wr2  = (const float*)d_in[9];
    float* out = (float*)d_out;

    cudaFuncSetAttribute(gemm2_mma, cudaFuncAttributeMaxDynamicSharedMemorySize, GT_SMEM);

    prep_kernel<<<PREP_HIST_BLOCKS + PREP_TOK_BLOCKS + PREP_W2_BLOCKS + PREP_E_BLOCKS,
                  256>>>(x, edge, emb, Wl1, Wr1, Wl2, Wr2);
    scan_fused<<<100, 256>>>();
    scatter_kernel<<<(N_EDGES / 4 + 255) / 256, 256>>>(edge);
    spmm_h1_kernel<<<(N_NODES * 32 + 255) / 256, 256>>>(bl1);
    spmm2_kernel<<<(N_MASK * 32 + 255) / 256, 256>>>(mask, edge);
    {
        dim3 grid(M_PAD / 128, 2048 / 128);
        gemm2_mma<<<grid, 256, GT_SMEM>>>(bl2);
    }
    softmax_kernel<<<N_MASK, 256>>>(out);
}

// round 17
// speedup vs baseline: 1.0436x; 1.0436x over previous
#include <cuda_runtime.h>
#include <cuda_bf16.h>
#include <math.h>
#include <stdint.h>

#define N_NODES 100000
#define N_EDGES 1600000
#define VOCAB   2048
#define DIM     64
#define N_MASK  10000
#define M_PAD   10112   // 79 * 128 (GEMM2 row tiles)

// ---------------- scratch (device globals: allocation-free) ----------------
__device__ int   g_deg[N_NODES];        // zero at load; re-zeroed by scan_fused
__device__ int   g_rowptr[N_NODES + 1];
__device__ int   g_cursor[N_NODES];
__device__ int   g_tok[N_NODES];
__device__ int   g_colpk[N_EDGES];      // src | (tok[src] << 17)
__device__ int   g_agg[100];
__device__ unsigned g_pub;              // scan publish counter (self-resetting)
__device__ unsigned g_fin;              // scan finish counter (self-resetting)
__device__ float g_El[VOCAB * DIM];     // emb @ W_l1
__device__ float g_Er[VOCAB * DIM];     // emb @ W_r1
__device__ float g_h1[N_NODES * DIM];
__device__ __nv_bfloat16 g_x2h[M_PAD * 128];   // A tile bf16 hi (pad rows stay 0)
__device__ __nv_bfloat16 g_x2l[M_PAD * 128];   // A tile bf16 lo
__device__ __nv_bfloat16 g_w2h[VOCAB * 128];   // B[n][k] bf16 hi, n-major
__device__ __nv_bfloat16 g_w2l[VOCAB * 128];   // B[n][k] bf16 lo
__device__ float g_logits[N_MASK * 2048];

__device__ __forceinline__ int ld_idx(const void* p, long i, int is64) {
    return is64 ? (int)((const long long*)p)[i] : ((const int*)p)[i];
}

// per-block dtype detect: int64 little-endian => odd 32-bit words all zero
__device__ __forceinline__ int detect_is64(const void* edge, int* sh) {
    if (threadIdx.x < 32) {
        int v = ((const int*)edge)[2 * threadIdx.x + 1];
        unsigned nz = __ballot_sync(0xffffffffu, v != 0);
        if (threadIdx.x == 0) *sh = (nz == 0u) ? 1 : 0;
    }
    __syncthreads();
    return *sh;
}

// load 4 consecutive indices starting at i (i multiple of 4)
__device__ __forceinline__ void ld_idx4(const void* p, long i, int is64, int* o) {
    if (is64) {
        longlong2 a = *(const longlong2*)((const long long*)p + i);
        longlong2 b = *(const longlong2*)((const long long*)p + i + 2);
        o[0] = (int)a.x; o[1] = (int)a.y; o[2] = (int)b.x; o[3] = (int)b.y;
    } else {
        int4 a = *(const int4*)((const int*)p + i);
        o[0] = a.x; o[1] = a.y; o[2] = a.z; o[3] = a.w;
    }
}

// ---------------- single-pass scan (100 resident blocks, spin barrier) ------
__global__ void scan_fused() {
    __shared__ int s[256];
    __shared__ int aggs[100];
    int b = blockIdx.x, t = threadIdx.x;
    int o = b * 1000 + t * 4;
    int d0 = 0, d1 = 0, d2 = 0, d3 = 0, sum = 0;
    if (t < 250) {
        d0 = g_deg[o]; d1 = g_deg[o + 1]; d2 = g_deg[o + 2]; d3 = g_deg[o + 3];
        sum = d0 + d1 + d2 + d3;
    }
    s[t] = sum; __syncthreads();
    for (int off = 1; off < 256; off <<= 1) {          // inclusive scan
        int x = (t >= off) ? s[t - off] : 0;
        __syncthreads();
        s[t] += x;
        __syncthreads();
    }
    int total = s[255];

    if (t == 0) {
        g_agg[b] = total;
        __threadfence();
        atomicAdd(&g_pub, 1u);
        while (atomicAdd(&g_pub, 0u) < 100u) {}
        __threadfence();
    }
    __syncthreads();
    if (t < 100) aggs[t] = g_agg[t];
    __syncthreads();

    int boff = 0;
    for (int i = 0; i < b; i++) boff += aggs[i];

    if (t < 250) {
        int run = boff + s[t] - sum;                   // exclusive prefix
        g_rowptr[o] = run;     g_cursor[o] = run;     run += d0;
        g_rowptr[o + 1] = run; g_cursor[o + 1] = run; run += d1;
        g_rowptr[o + 2] = run; g_cursor[o + 2] = run; run += d2;
        g_rowptr[o + 3] = run; g_cursor[o + 3] = run;
        g_deg[o] = 0; g_deg[o + 1] = 0; g_deg[o + 2] = 0; g_deg[o + 3] = 0;
    }
    if (b == 99 && t == 255) g_rowptr[N_NODES] = boff + total;

    __threadfence();
    if (t == 0) {
        unsigned f = atomicAdd(&g_fin, 1u);
        if (f == 99u) { g_pub = 0u; g_fin = 0u; }
    }
}

// =============== bf16 split helpers ========================================
static __device__ __forceinline__ uint32_t pack_bf2(float a, float b) {
    __nv_bfloat162 t = __floats2bfloat162_rn(a, b);
    return reinterpret_cast<uint32_t&>(t);
}
static __device__ __forceinline__ void split8(const float* v, uint4& hi, uint4& lo) {
    float r[8];
#pragma unroll
    for (int i = 0; i < 8; i++)
        r[i] = v[i] - __bfloat162float(__float2bfloat16(v[i]));
    hi = make_uint4(pack_bf2(v[0], v[1]), pack_bf2(v[2], v[3]),
                    pack_bf2(v[4], v[5]), pack_bf2(v[6], v[7]));
    lo = make_uint4(pack_bf2(r[0], r[1]), pack_bf2(r[2], r[3]),
                    pack_bf2(r[4], r[5]), pack_bf2(r[6], r[7]));
}
static __device__ __forceinline__ void split2(float2 v, uint32_t& hi, uint32_t& lo) {
    float rx = v.x - __bfloat162float(__float2bfloat16(v.x));
    float ry = v.y - __bfloat162float(__float2bfloat16(v.y));
    hi = pack_bf2(v.x, v.y);
    lo = pack_bf2(rx, ry);
}

#define MMA16816(d, a, b) \
    asm volatile( \
        "mma.sync.aligned.m16n8k16.row.col.f32.bf16.bf16.f32 " \
        "{%0,%1,%2,%3}, {%4,%5,%6,%7}, {%8,%9}, {%0,%1,%2,%3};" \
        : "+f"((d)[0]), "+f"((d)[1]), "+f"((d)[2]), "+f"((d)[3]) \
        : "r"((a)[0]), "r"((a)[1]), "r"((a)[2]), "r"((a)[3]), \
          "r"((b)[0]), "r"((b)[1]))

#define GSTR 136                             // bf16 per smem row (conflict-free)
#define GT_SMEM ((128 + 64) * 2 * GSTR * 2)  // 104448 B

// ---------- prep (fused): hist, g_tok, W2 split, E_l/E_r GEMM ---------------
#define PREP_HIST_BLOCKS 1563   // ceil(1600000/4/256)
#define PREP_TOK_BLOCKS 391     // ceil(100000/256)
#define PREP_W2_BLOCKS  128     // 32768/256
#define PREP_E_BLOCKS   256     // 2048 rows / 8 warps
__global__ void prep_kernel(const void* x, const void* edge,
                            const float* __restrict__ emb,
                            const float* __restrict__ Wl1,
                            const float* __restrict__ Wr1,
                            const float* __restrict__ Wl2,
                            const float* __restrict__ Wr2) {
    __shared__ float2 sWl[64 * 32];
    __shared__ float2 sWr[64 * 32];
    int b = blockIdx.x, t = threadIdx.x;
    if (b < PREP_HIST_BLOCKS) {
        __shared__ int sh;
        int is64 = detect_is64(edge, &sh);
        long e = (b * 256L + t) * 4;
        if (e >= N_EDGES) return;
        int d[4];
        ld_idx4(edge, N_EDGES + e, is64, d);
        atomicAdd(&g_deg[d[0]], 1);
        atomicAdd(&g_deg[d[1]], 1);
        atomicAdd(&g_deg[d[2]], 1);
        atomicAdd(&g_deg[d[3]], 1);
    } else if (b < PREP_HIST_BLOCKS + PREP_TOK_BLOCKS) {
        __shared__ int sh;
        int is64 = detect_is64(edge, &sh);
        int n = (b - PREP_HIST_BLOCKS) * 256 + t;
        if (n < N_NODES) g_tok[n] = ld_idx(x, n, is64);
    } else if (b < PREP_HIST_BLOCKS + PREP_TOK_BLOCKS + PREP_W2_BLOCKS) {
        int p = (b - PREP_HIST_BLOCKS - PREP_TOK_BLOCKS) * 256 + t;   // 0..32767
        int n = p & 2047, koct = p >> 11;
        const float* W = (koct < 8) ? Wl2 : Wr2;
        int kr0 = (koct * 8) & 63;
        float v[8];
#pragma unroll
        for (int j = 0; j < 8; j++)
            v[j] = W[(long)(kr0 + j) * 2048 + n];
        uint4 hi, lo;
        split8(v, hi, lo);
        *(uint4*)&g_w2h[n * 128 + koct * 8] = hi;
        *(uint4*)&g_w2l[n * 128 + koct * 8] = lo;
    } else {
        // E GEMM: 8 warps/block, warp per emb row
        int lane = t & 31, wid = t >> 5;
        for (int idx = t; idx < 64 * 32; idx += 256) {
            int k = idx >> 5, c = idx & 31;
            sWl[idx] = make_float2(Wl1[k * 64 + c], Wl1[k * 64 + 32 + c]);
            sWr[idx] = make_float2(Wr1[k * 64 + c], Wr1[k * 64 + 32 + c]);
        }
        __syncthreads();
        int row = (b - PREP_HIST_BLOCKS - PREP_TOK_BLOCKS - PREP_W2_BLOCKS) * 8 + wid;
        float e0 = emb[row * 64 + lane];
        float e1 = emb[row * 64 + 32 + lane];
        float al0 = 0.f, al1 = 0.f, ar0 = 0.f, ar1 = 0.f;
#pragma unroll
        for (int k = 0; k < 32; k++) {
            float ek = __shfl_sync(0xffffffffu, e0, k);
            float2 wl = sWl[k * 32 + lane];
            float2 wr = sWr[k * 32 + lane];
            al0 += ek * wl.x; al1 += ek * wl.y;
            ar0 += ek * wr.x; ar1 += ek * wr.y;
        }
#pragma unroll
        for (int k = 0; k < 32; k++) {
            float ek = __shfl_sync(0xffffffffu, e1, k);
            float2 wl = sWl[(k + 32) * 32 + lane];
            float2 wr = sWr[(k + 32) * 32 + lane];
            al0 += ek * wl.x; al1 += ek * wl.y;
            ar0 += ek * wr.x; ar1 += ek * wr.y;
        }
        g_El[row * 64 + lane] = al0;  g_El[row * 64 + 32 + lane] = al1;
        g_Er[row * 64 + lane] = ar0;  g_Er[row * 64 + 32 + lane] = ar1;
    }
}

// ---------------- scatter: writes src | (tok[src] << 17), 4 edges/thread ----
__global__ void scatter_kernel(const void* edge) {
    __shared__ int sh;
    int is64 = detect_is64(edge, &sh);
    long t = blockIdx.x * (long)blockDim.x + threadIdx.x;
    long e = t * 4;
    if (e >= N_EDGES) return;
    int s[4], d[4];
    ld_idx4(edge, e, is64, s);
    ld_idx4(edge, N_EDGES + e, is64, d);
    int tk0 = __ldg(&g_tok[s[0]]), tk1 = __ldg(&g_tok[s[1]]);
    int tk2 = __ldg(&g_tok[s[2]]), tk3 = __ldg(&g_tok[s[3]]);
    g_colpk[atomicAdd(&g_cursor[d[0]], 1)] = s[0] | (tk0 << 17);
    g_colpk[atomicAdd(&g_cursor[d[1]], 1)] = s[1] | (tk1 << 17);
    g_colpk[atomicAdd(&g_cursor[d[2]], 1)] = s[2] | (tk2 << 17);
    g_colpk[atomicAdd(&g_cursor[d[3]], 1)] = s[3] | (tk3 << 17);
}

// -------- fused SpMM mean + dense1: warp per node, float2 per lane ---------
// MLP=4; lane owns dims {2l, 2l+1}; no cross-lane reduction.
__global__ void spmm_h1_kernel(const float* __restrict__ bl1) {
    int nid = (blockIdx.x * blockDim.x + threadIdx.x) >> 5;
    int lane = threadIdx.x & 31;
    if (nid >= N_NODES) return;
    int start = g_rowptr[nid], end = g_rowptr[nid + 1];
    const float2* El2 = (const float2*)g_El;
    float2 a0 = make_float2(0.f, 0.f), a1 = a0, a2 = a0, a3 = a0;
    int p = start;
    for (; p + 3 < end; p += 4) {
        int t0 = ((unsigned)g_colpk[p])     >> 17;
        int t1 = ((unsigned)g_colpk[p + 1]) >> 17;
        int t2 = ((unsigned)g_colpk[p + 2]) >> 17;
        int t3 = ((unsigned)g_colpk[p + 3]) >> 17;
        float2 v0 = El2[t0 * 32 + lane];
        float2 v1 = El2[t1 * 32 + lane];
        float2 v2 = El2[t2 * 32 + lane];
        float2 v3 = El2[t3 * 32 + lane];
        a0.x += v0.x; a0.y += v0.y;
        a1.x += v1.x; a1.y += v1.y;
        a2.x += v2.x; a2.y += v2.y;
        a3.x += v3.x; a3.y += v3.y;
    }
    for (; p < end; p++) {
        int t0 = ((unsigned)g_colpk[p]) >> 17;
        float2 v0 = El2[t0 * 32 + lane];
        a0.x += v0.x; a0.y += v0.y;
    }
    a0.x += a1.x + a2.x + a3.x;
    a0.y += a1.y + a2.y + a3.y;
    float inv = 1.0f / fmaxf((float)(end - start), 1.0f);
    int tokn = g_tok[nid];
    float2 er = ((const float2*)g_Er)[tokn * 32 + lane];
    float2 bb = ((const float2*)bl1)[lane];
    float2 o = make_float2(fmaxf(a0.x * inv + er.x + bb.x, 0.f),
                           fmaxf(a0.y * inv + er.y + bb.y, 0.f));
    ((float2*)g_h1)[(long)nid * 32 + lane] = o;
}

// ---------------- SpMM mean, layer 2: warp per node, float2 per lane --------
__global__ void spmm2_kernel(const void* mask, const void* edge) {
    __shared__ int sh;
    int is64 = detect_is64(edge, &sh);
    int wid = (blockIdx.x * blockDim.x + threadIdx.x) >> 5;
    int lane = threadIdx.x & 31;
    if (wid >= N_MASK) return;
    int n = ld_idx(mask, wid, is64);
    int start = g_rowptr[n], end = g_rowptr[n + 1];
    const float2* h = (const float2*)g_h1;
    float2 a0 = make_float2(0.f, 0.f), a1 = a0, a2 = a0, a3 = a0;
    int p = start;
    for (; p + 3 < end; p += 4) {
        int s0 = g_colpk[p] & 0x1FFFF;
        int s1 = g_colpk[p + 1] & 0x1FFFF;
        int s2 = g_colpk[p + 2] & 0x1FFFF;
        int s3 = g_colpk[p + 3] & 0x1FFFF;
        float2 v0 = h[(long)s0 * 32 + lane];
        float2 v1 = h[(long)s1 * 32 + lane];
        float2 v2 = h[(long)s2 * 32 + lane];
        float2 v3 = h[(long)s3 * 32 + lane];
        a0.x += v0.x; a0.y += v0.y;
        a1.x += v1.x; a1.y += v1.y;
        a2.x += v2.x; a2.y += v2.y;
        a3.x += v3.x; a3.y += v3.y;
    }
    for (; p < end; p++) {
        int s0 = g_colpk[p] & 0x1FFFF;
        float2 v0 = h[(long)s0 * 32 + lane];
        a0.x += v0.x; a0.y += v0.y;
    }
    a0.x += a1.x + a2.x + a3.x;
    a0.y += a1.y + a2.y + a3.y;
    float inv = 1.0f / fmaxf((float)(end - start), 1.0f);
    float2 vm = make_float2(a0.x * inv, a0.y * inv);
    float2 vs = h[(long)n * 32 + lane];
    uint32_t mh, ml, sh2, sl;
    split2(vm, mh, ml);
    split2(vs, sh2, sl);
    long bm = (long)wid * 128 + lane * 2;       // mean part (dims 0..63)
    long bs = bm + 64;                          // self part (dims 64..127)
    *(uint32_t*)&g_x2h[bm] = mh;  *(uint32_t*)&g_x2l[bm] = ml;
    *(uint32_t*)&g_x2h[bs] = sh2; *(uint32_t*)&g_x2l[bs] = sl;
}

// ====== GEMM2: 128-row blocks, 2 col-tiles per CTA (A reused), 2 CTA/SM =====
__global__ void __launch_bounds__(256, 2) gemm2_mma(const float* __restrict__ bl2) {
    extern __shared__ __nv_bfloat16 sm[];
    __nv_bfloat16* AH = sm;
    __nv_bfloat16* AL = sm + 128 * GSTR;
    __nv_bfloat16* BH = sm + 2 * 128 * GSTR;
    __nv_bfloat16* BL = sm + 2 * 128 * GSTR + 64 * GSTR;

    int tid = threadIdx.x;
    int lane = tid & 31, wid = tid >> 5;
    int rowBase = blockIdx.x * 128;

    // load A tile once; reused for 2 col tiles
#pragma unroll
    for (int it = 0; it < 8; it++) {
        int p = tid + it * 256;
        int m = p >> 4, koct = p & 15;
        long src = (long)(rowBase + m) * 128 + koct * 8;
        *(uint4*)&AH[m * GSTR + koct * 8] = *(const uint4*)&g_x2h[src];
        *(uint4*)&AL[m * GSTR + koct * 8] = *(const uint4*)&g_x2l[src];
    }

    int tig = lane & 3, grp = lane >> 2;
    int wm = (wid & 3) * 32;
    int wn = (wid >> 2) * 32;

#pragma unroll
    for (int ct = 0; ct < 2; ct++) {
        int colBase = (blockIdx.y * 2 + ct) * 64;
        __syncthreads();   // B consumers of prev iter done (covers A on ct=0)
#pragma unroll
        for (int it = 0; it < 4; it++) {
            int p = tid + it * 256;
            int n = p >> 4, koct = p & 15;
            long src = (long)(colBase + n) * 128 + koct * 8;
            *(uint4*)&BH[n * GSTR + koct * 8] = *(const uint4*)&g_w2h[src];
            *(uint4*)&BL[n * GSTR + koct * 8] = *(const uint4*)&g_w2l[src];
        }
        __syncthreads();

        float acc[2][4][4] = {};
#pragma unroll
        for (int ks = 0; ks < 8; ks++) {
            int kw = ks * 8 + tig;
            uint32_t aH[2][4], aL[2][4], bH[4][2], bL[4][2];
#pragma unroll
            for (int mt = 0; mt < 2; mt++) {
                const __nv_bfloat16* pH = &AH[(wm + mt * 16 + grp) * GSTR + kw * 2];
                const __nv_bfloat16* pL = &AL[(wm + mt * 16 + grp) * GSTR + kw * 2];
                aH[mt][0] = *(const uint32_t*)pH;
                aH[mt][1] = *(const uint32_t*)(pH + 8 * GSTR);
                aH[mt][2] = *(const uint32_t*)(pH + 8);
                aH[mt][3] = *(const uint32_t*)(pH + 8 * GSTR + 8);
                aL[mt][0] = *(const uint32_t*)pL;
                aL[mt][1] = *(const uint32_t*)(pL + 8 * GSTR);
                aL[mt][2] = *(const uint32_t*)(pL + 8);
                aL[mt][3] = *(const uint32_t*)(pL + 8 * GSTR + 8);
            }
#pragma unroll
            for (int nt = 0; nt < 4; nt++) {
                const __nv_bfloat16* pH = &BH[(wn + nt * 8 + grp) * GSTR + kw * 2];
                const __nv_bfloat16* pL = &BL[(wn + nt * 8 + grp) * GSTR + kw * 2];
                bH[nt][0] = *(const uint32_t*)pH;
                bH[nt][1] = *(const uint32_t*)(pH + 8);
                bL[nt][0] = *(const uint32_t*)pL;
                bL[nt][1] = *(const uint32_t*)(pL + 8);
            }
#pragma unroll
            for (int mt = 0; mt < 2; mt++)
#pragma unroll
                for (int nt = 0; nt < 4; nt++) {
                    MMA16816(acc[mt][nt], aH[mt], bH[nt]);
                    MMA16816(acc[mt][nt], aH[mt], bL[nt]);
                    MMA16816(acc[mt][nt], aL[mt], bH[nt]);
                }
        }

#pragma unroll
        for (int mt = 0; mt < 2; mt++) {
#pragma unroll
            for (int nt = 0; nt < 4; nt++) {
                int row = rowBase + wm + mt * 16 + grp;
                int col = colBase + wn + nt * 8 + tig * 2;
                float2 bv = *(const float2*)&bl2[col];
                if (row < N_MASK) {
                    float2 o = make_float2(acc[mt][nt][0] + bv.x, acc[mt][nt][1] + bv.y);
                    *(float2*)&g_logits[(long)row * 2048 + col] = o;
                }
                if (row + 8 < N_MASK) {
                    float2 o = make_float2(acc[mt][nt][2] + bv.x, acc[mt][nt][3] + bv.y);
                    *(float2*)&g_logits[(long)(row + 8) * 2048 + col] = o;
                }
            }
        }
    }
}

// ---------------- row-wise log_softmax --------------------------------------
__global__ void softmax_kernel(float* out) {
    __shared__ float sred[256];
    int r = blockIdx.x;
    int t = threadIdx.x;
    const float4* L = (const float4*)&g_logits[(long)r * 2048];
    float4 v0 = L[t], v1 = L[t + 256];

    float mx = fmaxf(fmaxf(fmaxf(v0.x, v0.y), fmaxf(v0.z, v0.w)),
                     fmaxf(fmaxf(v1.x, v1.y), fmaxf(v1.z, v1.w)));
    sred[t] = mx; __syncthreads();
    for (int s = 128; s > 0; s >>= 1) {
        if (t < s) sred[t] = fmaxf(sred[t], sred[t + s]);
        __syncthreads();
    }
    mx = sred[0];
    __syncthreads();

    float sum = __expf(v0.x - mx) + __expf(v0.y - mx) + __expf(v0.z - mx) + __expf(v0.w - mx)
              + __expf(v1.x - mx) + __expf(v1.y - mx) + __expf(v1.z - mx) + __expf(v1.w - mx);
    sred[t] = sum; __syncthreads();
    for (int s = 128; s > 0; s >>= 1) {
        if (t < s) sred[t] += sred[t + s];
        __syncthreads();
    }
    float shift = mx + __logf(sred[0]);

    float4* O = (float4*)&out[(long)r * 2048];
    O[t]       = make_float4(v0.x - shift, v0.y - shift, v0.z - shift, v0.w - shift);
    O[t + 256] = make_float4(v1.x - shift, v1.y - shift, v1.z - shift, v1.w - shift);
}

// ---------------- launch ----------------------------------------------------
extern "C" void kernel_launch(void* const* d_in, const int* in_sizes, int n_in,
                              void* d_out, int out_size) {
    const void*  x    = d_in[0];
    const void*  edge = d_in[1];
    const void*  mask = d_in[2];
    const float* emb  = (const float*)d_in[3];
    const float* Wl1  = (const float*)d_in[4];
    const float* bl1  = (const float*)d_in[5];
    const float* Wr1  = (const float*)d_in[6];
    const float* Wl2  = (const float*)d_in[7];
    const float* bl2  = (const float*)d_in[8];
    const float* Wr2  = (const float*)d_in[9];
    float* out = (float*)d_out;

    cudaFuncSetAttribute(gemm2_mma, cudaFuncAttributeMaxDynamicSharedMemorySize, GT_SMEM);

    prep_kernel<<<PREP_HIST_BLOCKS + PREP_TOK_BLOCKS + PREP_W2_BLOCKS + PREP_E_BLOCKS,
                  256>>>(x, edge, emb, Wl1, Wr1, Wl2, Wr2);
    scan_fused<<<100, 256>>>();
    scatter_kernel<<<(N_EDGES / 4 + 255) / 256, 256>>>(edge);
    spmm_h1_kernel<<<(N_NODES * 32 + 255) / 256, 256>>>(bl1);
    spmm2_kernel<<<(N_MASK * 32 + 255) / 256, 256>>>(mask, edge);
    {
        dim3 grid(M_PAD / 128, 2048 / 128);
        gemm2_mma<<<grid, 256, GT_SMEM>>>(bl2);
    }
    softmax_kernel<<<N_MASK, 256>>>(out);
}